// round 15
// baseline (speedup 1.0000x reference)
#include <cuda_runtime.h>
#include <cuda_fp16.h>
#include <math.h>

#define N_NODES 50000
#define N_EDGES 800000
#define D       128
#define DE      10
#define BN_EPS  1e-5f
#define N_CHUNK 782           // ceil(50000 / 64)
#define NB1     2048          // stats stage-1 blocks

typedef unsigned long long ull;

// Scratch (device globals: allocation-free)
// P16 per node: 512 halves in two 256-half blocks.
//   src block [0:256):  granule l (l=0..31) = {g1[4l..4l+3], c1[4l..4l+3]}
//   dst block [256:512): granule l = {g2[4l..4l+3], c2[4l..4l+3]}
__device__ __half  g_P16[N_NODES * 512];
__device__ __half  g_w16[4 * 128 * 128];   // [q][k][c]
__device__ float   g_agg[N_NODES * D];
__device__ float   g_part[2 * D * NB1];    // [sum|sq][d][b]
__device__ double  g_sum[D];
__device__ double  g_sumsq[D];
__device__ int     g_is64;

__device__ __forceinline__ float softplus_f(float x) {
    return fmaxf(x, 0.0f) + __logf(1.0f + __expf(-fabsf(x)));
}
__device__ __forceinline__ float sigmoid_f(float x) {
    // 1 MUFU via tanh.approx (vs ex2 + fp32 division)
    float y;
    asm("tanh.approx.f32 %0, %1;" : "=f"(y) : "f"(0.5f * x));
    return fmaf(0.5f, y, 0.5f);
}

// ---- mma / ldmatrix wrappers ----
__device__ __forceinline__ unsigned smem_u32(const void* p) {
    return (unsigned)__cvta_generic_to_shared(p);
}
__device__ __forceinline__ void ldsm_x4(unsigned& a0, unsigned& a1,
                                        unsigned& a2, unsigned& a3, unsigned addr) {
    asm volatile("ldmatrix.sync.aligned.m8n8.x4.shared.b16 {%0,%1,%2,%3}, [%4];"
                 : "=r"(a0), "=r"(a1), "=r"(a2), "=r"(a3) : "r"(addr));
}
__device__ __forceinline__ void ldsm_x2t(unsigned& b0, unsigned& b1, unsigned addr) {
    asm volatile("ldmatrix.sync.aligned.m8n8.x2.trans.shared.b16 {%0,%1}, [%2];"
                 : "=r"(b0), "=r"(b1) : "r"(addr));
}
__device__ __forceinline__ void mma16816(float* d, const unsigned* a, const unsigned* b) {
    asm volatile(
        "mma.sync.aligned.m16n8k16.row.col.f32.f16.f16.f32 "
        "{%0,%1,%2,%3}, {%4,%5,%6,%7}, {%8,%9}, {%0,%1,%2,%3};"
        : "+f"(d[0]), "+f"(d[1]), "+f"(d[2]), "+f"(d[3])
        : "r"(a[0]), "r"(a[1]), "r"(a[2]), "r"(a[3]), "r"(b[0]), "r"(b[1]));
}

// P16 offset for logical (quadrant q, channel d) within a node's 512 halves
__device__ __host__ __forceinline__ int p16_off(int q, int d) {
    return ((q >> 1) ? 256 : 0) + (d >> 2) * 8 + ((q & 1) ? 4 : 0) + (d & 3);
}

// ---------------------------------------------------------------------------
// Kernel 1: zero agg + convert W -> fp16 + detect  (h16 buffer eliminated)
// ---------------------------------------------------------------------------
__global__ void prep_kernel(const float* __restrict__ gw,
                            const float* __restrict__ cw,
                            const int* __restrict__ ei32) {
    const int total4 = N_NODES * D / 4;
    float4 z = make_float4(0.f, 0.f, 0.f, 0.f);
    int gid = blockIdx.x * blockDim.x + threadIdx.x;
    for (int i = gid; i < total4; i += gridDim.x * blockDim.x)
        ((float4*)g_agg)[i] = z;
    if (gid < 4 * 128 * 128 / 2) {   // 2 elements each
        int i = gid * 2;
        int q = i >> 14, k = (i >> 7) & 127, c = i & 127;
        const float* W = (q & 1) ? cw : gw;
        float2 wv = *(const float2*)&W[(size_t)((q >> 1) * 128 + k) * 128 + c];
        *(__half2*)&g_w16[i] = __floats2half2_rn(wv.x, wv.y);
    }
    if (gid == 0) {
        int nz = 0;
        #pragma unroll
        for (int j = 0; j < 64; ++j) nz |= ei32[2 * j + 1];
        g_is64 = (nz == 0) ? 1 : 0;
    }
}

// ---------------------------------------------------------------------------
// Kernel 2: node projection GEMM on tensor cores (HMMA m16n8k16).
// Reads h fp32 directly (in-register fp16 convert), 64-row chunks = 4 MMA
// tiles per barrier pair. Epilogue -> interleaved P16 via p16_off().
// ---------------------------------------------------------------------------
__global__ __launch_bounds__(256) void node_gemm_tc(
    const float* __restrict__ h,
    const float* __restrict__ gb, const float* __restrict__ cb)
{
    __shared__ __half S[128 * 136];   // W staging; A chunks use rows 0-63

    const int q    = blockIdx.y;
    const int tid  = threadIdx.x;
    const int w    = tid >> 5;
    const int lane = tid & 31;
    const unsigned sbase = smem_u32(S);

    // ---- stage W quadrant, extract B fragments ----
    const __half* wq = g_w16 + (size_t)q * 16384;
    #pragma unroll
    for (int j = 0; j < 8; ++j) {
        int i = tid + j * 256;
        int row = i >> 4, colh = (i & 15) * 8;
        *(uint4*)&S[row * 136 + colh] = *(const uint4*)&wq[row * 128 + colh];
    }
    __syncthreads();

    unsigned Bf[8][2][2];
    {
        int krow = lane & 15;
        #pragma unroll
        for (int ks = 0; ks < 8; ++ks)
            #pragma unroll
            for (int nt = 0; nt < 2; ++nt) {
                int cbase = w * 16 + nt * 8;
                unsigned addr = sbase +
                    ((unsigned)((ks * 16 + krow) * 136 + cbase) << 1);
                ldsm_x2t(Bf[ks][nt][0], Bf[ks][nt][1], addr);
            }
    }

    int ccol0 = w * 16 + (lane & 3) * 2;
    float bx0 = 0.f, by0 = 0.f, bx1 = 0.f, by1 = 0.f;
    if (q == 0) {
        bx0 = gb[ccol0];     by0 = gb[ccol0 + 1];
        bx1 = gb[ccol0 + 8]; by1 = gb[ccol0 + 9];
    } else if (q == 1) {
        bx0 = cb[ccol0];     by0 = cb[ccol0 + 1];
        bx1 = cb[ccol0 + 8]; by1 = cb[ccol0 + 9];
    }

    const int arow = lane & 15;
    const int acol = (lane >> 4) * 8;
    const int off0 = p16_off(q, ccol0);
    const int off1 = p16_off(q, ccol0 + 8);

    for (int mc = blockIdx.x; mc < N_CHUNK; mc += gridDim.x) {
        const int row0 = mc * 64;
        __syncthreads();   // protect S from previous iteration readers
        // stage A: 64 rows x 128 cols, fp32 -> fp16 in-register
        #pragma unroll
        for (int j = 0; j < 8; ++j) {
            int idx = tid + j * 256;            // 2048 float4 loads
            int r = idx >> 5, c4 = (idx & 31) * 4;
            float4 v = make_float4(0.f, 0.f, 0.f, 0.f);
            if (row0 + r < N_NODES)
                v = *(const float4*)&h[(size_t)(row0 + r) * 128 + c4];
            __half2 a = __floats2half2_rn(v.x, v.y);
            __half2 b = __floats2half2_rn(v.z, v.w);
            *(uint2*)&S[r * 136 + c4] = make_uint2(*(unsigned*)&a, *(unsigned*)&b);
        }
        __syncthreads();

        #pragma unroll
        for (int t = 0; t < 4; ++t) {
            float acc0[4] = {0.f, 0.f, 0.f, 0.f};
            float acc1[4] = {0.f, 0.f, 0.f, 0.f};
            #pragma unroll
            for (int ks = 0; ks < 8; ++ks) {
                unsigned a[4];
                unsigned addr = sbase +
                    ((unsigned)((t * 16 + arow) * 136 + ks * 16 + acol) << 1);
                ldsm_x4(a[0], a[1], a[2], a[3], addr);
                mma16816(acc0, a, Bf[ks][0]);
                mma16816(acc1, a, Bf[ks][1]);
            }

            int r0 = row0 + t * 16 + (lane >> 2);
            if (r0 < N_NODES) {
                size_t base = (size_t)r0 * 512;
                __half2 v;
                v = __floats2half2_rn(acc0[0] + bx0, acc0[1] + by0);
                *(__half2*)&g_P16[base + off0] = v;
                v = __floats2half2_rn(acc1[0] + bx1, acc1[1] + by1);
                *(__half2*)&g_P16[base + off1] = v;
            }
            if (r0 + 8 < N_NODES) {
                size_t base = (size_t)(r0 + 8) * 512;
                __half2 v;
                v = __floats2half2_rn(acc0[2] + bx0, acc0[3] + by0);
                *(__half2*)&g_P16[base + off0] = v;
                v = __floats2half2_rn(acc1[2] + bx1, acc1[3] + by1);
                *(__half2*)&g_P16[base + off1] = v;
            }
        }
    }
}

// ---------------------------------------------------------------------------
// Kernel 3: edge stage — interleaved P16 (1 LDG.128/endpoint), fp16 W3 in
// shared, PACKED-PAIR shfl broadcast (2 edges per shfl, split via half-lane
// selectors), 4 edges/warp iter, persistent 1-wave grid, red.v4 scatter.
// ---------------------------------------------------------------------------
__global__ __launch_bounds__(128, 10) void edge_kernel(
    const void*  __restrict__ ei,
    const float* __restrict__ ef,
    const float* __restrict__ gw, const float* __restrict__ cw)
{
    // s_w[k][lane] = {g(d0,d1), g(d2,d3), c(d0,d1), c(d2,d3)} as half2s
    __shared__ uint4 s_w[DE][32];

    const int tid    = threadIdx.x;
    const int lane   = tid & 31;
    const int warp   = (blockIdx.x * blockDim.x + tid) >> 5;
    const int nwarps = (gridDim.x * blockDim.x) >> 5;
    const int is64   = g_is64;

    for (int i = tid; i < DE * 32; i += blockDim.x) {
        int k = i >> 5, p = i & 31;
        float4 g = *(const float4*)&gw[(size_t)(256 + k) * 128 + p * 4];
        float4 c = *(const float4*)&cw[(size_t)(256 + k) * 128 + p * 4];
        __half2 g0 = __floats2half2_rn(g.x, g.y);
        __half2 g1 = __floats2half2_rn(g.z, g.w);
        __half2 c0 = __floats2half2_rn(c.x, c.y);
        __half2 c1 = __floats2half2_rn(c.z, c.w);
        s_w[k][p] = make_uint4(*(unsigned*)&g0, *(unsigned*)&g1,
                               *(unsigned*)&c0, *(unsigned*)&c1);
    }
    __syncthreads();

    for (int e = warp * 4; e < N_EDGES; e += nwarps * 4) {
        int s[4], d[4];
        if (is64) {
            const long long* E = (const long long*)ei;
            #pragma unroll
            for (int j = 0; j < 4; ++j) {
                s[j] = (int)E[e + j];
                d[j] = (int)E[N_EDGES + e + j];
            }
        } else {
            const int* E = (const int*)ei;
            #pragma unroll
            for (int j = 0; j < 4; ++j) {
                s[j] = E[e + j];
                d[j] = E[N_EDGES + e + j];
            }
        }

        // 8 independent 16B gathers; accumulators init = g1+g2 / c1+c2
        __half2 rg0[4], rg1[4], rc0[4], rc1[4];
        #pragma unroll
        for (int j = 0; j < 4; ++j) {
            uint4 S4 = *(const uint4*)(g_P16 + (size_t)s[j] * 512 + lane * 8);
            uint4 D4 = *(const uint4*)(g_P16 + (size_t)d[j] * 512 + 256 + lane * 8);
            rg0[j] = __hadd2(*(__half2*)&S4.x, *(__half2*)&D4.x);
            rg1[j] = __hadd2(*(__half2*)&S4.y, *(__half2*)&D4.y);
            rc0[j] = __hadd2(*(__half2*)&S4.z, *(__half2*)&D4.z);
            rc1[j] = __hadd2(*(__half2*)&S4.w, *(__half2*)&D4.w);
        }

        // pair-packed edge features: evp[p] = (ev[2p], ev[2p+1]) as half2
        unsigned evp[2];
        #pragma unroll
        for (int p = 0; p < 2; ++p) {
            float eA = (lane < DE) ? ef[(size_t)(e + 2 * p) * DE + lane] : 0.f;
            float eB = (lane < DE) ? ef[(size_t)(e + 2 * p + 1) * DE + lane] : 0.f;
            __half2 t = __floats2half2_rn(eA, eB);
            evp[p] = *(unsigned*)&t;
        }

        // rank-10 update in half2; ONE shfl serves TWO edges (half-lane split)
        #pragma unroll
        for (int k = 0; k < DE; ++k) {
            uint4 wv = s_w[k][lane];
            __half2 wG0 = *(__half2*)&wv.x, wG1 = *(__half2*)&wv.y;
            __half2 wC0 = *(__half2*)&wv.z, wC1 = *(__half2*)&wv.w;
            #pragma unroll
            for (int p = 0; p < 2; ++p) {
                unsigned eku = __shfl_sync(0xffffffffu, evp[p], k);
                __half2 ek2 = *(__half2*)&eku;
                __half2 e0 = __low2half2(ek2);    // folds to .H0_H0
                __half2 e1 = __high2half2(ek2);   // folds to .H1_H1
                int j0 = 2 * p, j1 = 2 * p + 1;
                rg0[j0] = __hfma2(e0, wG0, rg0[j0]);
                rg1[j0] = __hfma2(e0, wG1, rg1[j0]);
                rc0[j0] = __hfma2(e0, wC0, rc0[j0]);
                rc1[j0] = __hfma2(e0, wC1, rc1[j0]);
                rg0[j1] = __hfma2(e1, wG0, rg0[j1]);
                rg1[j1] = __hfma2(e1, wG1, rg1[j1]);
                rc0[j1] = __hfma2(e1, wC0, rc0[j1]);
                rc1[j1] = __hfma2(e1, wC1, rc1[j1]);
            }
        }

        // activations (f32) + scatter; output cols = {4*lane..4*lane+3}
        #pragma unroll
        for (int j = 0; j < 4; ++j) {
            float2 gA = __half22float2(rg0[j]);
            float2 gB = __half22float2(rg1[j]);
            float2 cA = __half22float2(rc0[j]);
            float2 cB = __half22float2(rc1[j]);
            float4 m;
            m.x = sigmoid_f(gA.x) * softplus_f(cA.x);
            m.y = sigmoid_f(gA.y) * softplus_f(cA.y);
            m.z = sigmoid_f(gB.x) * softplus_f(cB.x);
            m.w = sigmoid_f(gB.y) * softplus_f(cB.y);
            float* o = g_agg + (size_t)s[j] * D + lane * 4;
            asm volatile("red.global.add.v4.f32 [%0], {%1,%2,%3,%4};"
                         :: "l"(o), "f"(m.x), "f"(m.y), "f"(m.z), "f"(m.w)
                         : "memory");
        }
    }
}

// ---------------------------------------------------------------------------
// Kernel 4a: BN stats stage 1 — 2048 blocks, thread d = channel d, 8-way ILP.
// NO atomics: per-block partials to g_part[d][b] (transposed for stage 2).
// ---------------------------------------------------------------------------
__global__ __launch_bounds__(128) void stats1_kernel() {
    const int d = threadIdx.x;   // blockDim = 128
    const int b = blockIdx.x;
    const int chunk = (N_NODES + NB1 - 1) / NB1;   // 25
    const int n0 = b * chunk;
    const int n1 = min(n0 + chunk, N_NODES);

    float s[8], q[8];
    #pragma unroll
    for (int u = 0; u < 8; ++u) { s[u] = 0.f; q[u] = 0.f; }

    int n = n0;
    for (; n + 8 <= n1; n += 8) {
        #pragma unroll
        for (int u = 0; u < 8; ++u) {
            float v = g_agg[(size_t)(n + u) * D + d];
            s[u] += v; q[u] = fmaf(v, v, q[u]);
        }
    }
    for (; n < n1; ++n) {
        float v = g_agg[(size_t)n * D + d];
        s[0] += v; q[0] = fmaf(v, v, q[0]);
    }
    float ss = ((s[0] + s[1]) + (s[2] + s[3])) + ((s[4] + s[5]) + (s[6] + s[7]));
    float qq = ((q[0] + q[1]) + (q[2] + q[3])) + ((q[4] + q[5]) + (q[6] + q[7]));
    g_part[d * NB1 + b] = ss;
    g_part[D * NB1 + d * NB1 + b] = qq;
}

// ---------------------------------------------------------------------------
// Kernel 4b: BN stats stage 2 — one block per channel, tree reduce, no atomics
// ---------------------------------------------------------------------------
__global__ __launch_bounds__(256) void stats2_kernel() {
    __shared__ float rs[256], rq[256];
    const int d = blockIdx.x;
    const int t = threadIdx.x;

    float s = 0.f, q = 0.f;
    #pragma unroll
    for (int b = t; b < NB1; b += 256) {
        s += g_part[d * NB1 + b];
        q += g_part[D * NB1 + d * NB1 + b];
    }
    rs[t] = s; rq[t] = q;
    __syncthreads();
    #pragma unroll
    for (int off = 128; off > 0; off >>= 1) {
        if (t < off) { rs[t] += rs[t + off]; rq[t] += rq[t + off]; }
        __syncthreads();
    }
    if (t == 0) {
        g_sum[d]   = (double)rs[0];
        g_sumsq[d] = (double)rq[0];
    }
}

// ---------------------------------------------------------------------------
// Kernel 5: BN affine fold (per-block, in smem) + apply + residual + softplus
// ---------------------------------------------------------------------------
__global__ __launch_bounds__(256) void final_kernel(
    const float* __restrict__ h,
    const float* __restrict__ gamma, const float* __restrict__ beta,
    float* __restrict__ out)
{
    __shared__ float sa[D], sb[D];
    if (threadIdx.x < D) {
        int d = threadIdx.x;
        double mean = g_sum[d] * (1.0 / N_NODES);
        double var  = g_sumsq[d] * (1.0 / N_NODES) - mean * mean;
        float invstd = rsqrtf((float)var + BN_EPS);
        float a = invstd * gamma[d];
        sa[d] = a;
        sb[d] = beta[d] - (float)mean * a;
    }
    __syncthreads();

    const int total4 = N_NODES * D / 4;
    for (int f4 = blockIdx.x * blockDim.x + threadIdx.x; f4 < total4;
         f4 += gridDim.x * blockDim.x) {
        int d4 = (f4 & 31) * 4;
        float4 av = ((const float4*)g_agg)[f4];
        float4 hv = ((const float4*)h)[f4];
        float4 aa = *(const float4*)&sa[d4];
        float4 bb = *(const float4*)&sb[d4];
        float4 r;
        r.x = softplus_f(hv.x + av.x * aa.x + bb.x);
        r.y = softplus_f(hv.y + av.y * aa.y + bb.y);
        r.z = softplus_f(hv.z + av.z * aa.z + bb.z);
        r.w = softplus_f(hv.w + av.w * aa.w + bb.w);
        ((float4*)out)[f4] = r;
    }
}

// ---------------------------------------------------------------------------
extern "C" void kernel_launch(void* const* d_in, const int* in_sizes, int n_in,
                              void* d_out, int out_size) {
    const float* h     = (const float*)d_in[0];
    const void*  ei    = d_in[1];
    const float* ef    = (const float*)d_in[2];
    const float* gw    = (const float*)d_in[3];
    const float* gb    = (const float*)d_in[4];
    const float* cw    = (const float*)d_in[5];
    const float* cb    = (const float*)d_in[6];
    const float* gamma = (const float*)d_in[7];
    const float* beta  = (const float*)d_in[8];
    float* out = (float*)d_out;

    prep_kernel<<<1024, 256>>>(gw, cw, (const int*)ei);
    dim3 gg(196, 4);
    node_gemm_tc<<<gg, 256>>>(h, gb, cb);
    edge_kernel<<<1480, 128>>>(ei, ef, gw, cw);
    stats1_kernel<<<NB1, 128>>>();
    stats2_kernel<<<D, 256>>>();
    final_kernel<<<1024, 256>>>(h, gamma, beta, out);
}

// round 16
// speedup vs baseline: 1.5654x; 1.5654x over previous
#include <cuda_runtime.h>
#include <cuda_fp16.h>
#include <math.h>

#define N_NODES 50000
#define N_EDGES 800000
#define D       128
#define DE      10
#define BN_EPS  1e-5f
#define M_TILES 3125          // 50000 / 16
#define NB1     2048          // stats stage-1 blocks

typedef unsigned long long ull;

// Scratch (device globals: allocation-free)
// P16 per node: 512 halves in two 256-half blocks.
//   src block [0:256):  granule l (l=0..31) = {g1[4l..4l+3], c1[4l..4l+3]}
//   dst block [256:512): granule l = {g2[4l..4l+3], c2[4l..4l+3]}
__device__ __half  g_P16[N_NODES * 512];
__device__ __half  g_h16[N_NODES * D];
__device__ __half  g_w16[4 * 128 * 128];   // [q][k][c]
__device__ float   g_agg[N_NODES * D];
__device__ float   g_part[2 * D * NB1];    // [sum|sq][d][b]
__device__ double  g_sum[D];
__device__ double  g_sumsq[D];
__device__ int     g_is64;

__device__ __forceinline__ float softplus_f(float x) {
    return fmaxf(x, 0.0f) + __logf(1.0f + __expf(-fabsf(x)));
}
__device__ __forceinline__ float sigmoid_f(float x) {
    // 1 MUFU via tanh.approx (vs ex2 + fp32 division)
    float y;
    asm("tanh.approx.f32 %0, %1;" : "=f"(y) : "f"(0.5f * x));
    return fmaf(0.5f, y, 0.5f);
}

// ---- mma / ldmatrix wrappers ----
__device__ __forceinline__ unsigned smem_u32(const void* p) {
    return (unsigned)__cvta_generic_to_shared(p);
}
__device__ __forceinline__ void ldsm_x4(unsigned& a0, unsigned& a1,
                                        unsigned& a2, unsigned& a3, unsigned addr) {
    asm volatile("ldmatrix.sync.aligned.m8n8.x4.shared.b16 {%0,%1,%2,%3}, [%4];"
                 : "=r"(a0), "=r"(a1), "=r"(a2), "=r"(a3) : "r"(addr));
}
__device__ __forceinline__ void ldsm_x2t(unsigned& b0, unsigned& b1, unsigned addr) {
    asm volatile("ldmatrix.sync.aligned.m8n8.x2.trans.shared.b16 {%0,%1}, [%2];"
                 : "=r"(b0), "=r"(b1) : "r"(addr));
}
__device__ __forceinline__ void mma16816(float* d, const unsigned* a, const unsigned* b) {
    asm volatile(
        "mma.sync.aligned.m16n8k16.row.col.f32.f16.f16.f32 "
        "{%0,%1,%2,%3}, {%4,%5,%6,%7}, {%8,%9}, {%0,%1,%2,%3};"
        : "+f"(d[0]), "+f"(d[1]), "+f"(d[2]), "+f"(d[3])
        : "r"(a[0]), "r"(a[1]), "r"(a[2]), "r"(a[3]), "r"(b[0]), "r"(b[1]));
}

// P16 offset for logical (quadrant q, channel d) within a node's 512 halves
__device__ __host__ __forceinline__ int p16_off(int q, int d) {
    return ((q >> 1) ? 256 : 0) + (d >> 2) * 8 + ((q & 1) ? 4 : 0) + (d & 3);
}

// ---------------------------------------------------------------------------
// Kernel 1: zero agg + convert h -> fp16 + convert W -> fp16 + detect
// ---------------------------------------------------------------------------
__global__ void prep_kernel(const float* __restrict__ h,
                            const float* __restrict__ gw,
                            const float* __restrict__ cw,
                            const int* __restrict__ ei32) {
    const int total4 = N_NODES * D / 4;
    float4 z = make_float4(0.f, 0.f, 0.f, 0.f);
    int gid = blockIdx.x * blockDim.x + threadIdx.x;
    for (int i = gid; i < total4; i += gridDim.x * blockDim.x) {
        ((float4*)g_agg)[i] = z;
        float4 v = ((const float4*)h)[i];
        __half2 a = __floats2half2_rn(v.x, v.y);
        __half2 b = __floats2half2_rn(v.z, v.w);
        ((uint2*)g_h16)[i] = make_uint2(*(unsigned*)&a, *(unsigned*)&b);
    }
    if (gid < 4 * 128 * 128 / 2) {   // 2 elements each
        int i = gid * 2;
        int q = i >> 14, k = (i >> 7) & 127, c = i & 127;
        const float* W = (q & 1) ? cw : gw;
        float2 wv = *(const float2*)&W[(size_t)((q >> 1) * 128 + k) * 128 + c];
        *(__half2*)&g_w16[i] = __floats2half2_rn(wv.x, wv.y);
    }
    if (gid == 0) {
        int nz = 0;
        #pragma unroll
        for (int j = 0; j < 64; ++j) nz |= ei32[2 * j + 1];
        g_is64 = (nz == 0) ? 1 : 0;
    }
}

// ---------------------------------------------------------------------------
// Kernel 2: node projection GEMM on tensor cores (HMMA m16n8k16).
// Double-buffered A staging (S rows 0-15 / 16-31): ONE barrier per tile and
// the next tile's h16 LDG issued before this tile's MMAs.
// Epilogue stores into the interleaved P16 layout via p16_off().
// ---------------------------------------------------------------------------
__global__ __launch_bounds__(256) void node_gemm_tc(
    const float* __restrict__ gb, const float* __restrict__ cb)
{
    __shared__ __half S[128 * 136];

    const int q    = blockIdx.y;
    const int tid  = threadIdx.x;
    const int w    = tid >> 5;
    const int lane = tid & 31;
    const unsigned sbase = smem_u32(S);

    const __half* wq = g_w16 + (size_t)q * 16384;
    #pragma unroll
    for (int j = 0; j < 8; ++j) {
        int i = tid + j * 256;
        int row = i >> 4, colh = (i & 15) * 8;
        *(uint4*)&S[row * 136 + colh] = *(const uint4*)&wq[row * 128 + colh];
    }
    __syncthreads();

    unsigned Bf[8][2][2];
    {
        int krow = lane & 15;
        #pragma unroll
        for (int ks = 0; ks < 8; ++ks)
            #pragma unroll
            for (int nt = 0; nt < 2; ++nt) {
                int cbase = w * 16 + nt * 8;
                unsigned addr = sbase +
                    ((unsigned)((ks * 16 + krow) * 136 + cbase) << 1);
                ldsm_x2t(Bf[ks][nt][0], Bf[ks][nt][1], addr);
            }
    }
    __syncthreads();   // Bf extraction reads S before A staging overwrites it

    int ccol0 = w * 16 + (lane & 3) * 2;
    float bx0 = 0.f, by0 = 0.f, bx1 = 0.f, by1 = 0.f;
    if (q == 0) {
        bx0 = gb[ccol0];     by0 = gb[ccol0 + 1];
        bx1 = gb[ccol0 + 8]; by1 = gb[ccol0 + 9];
    } else if (q == 1) {
        bx0 = cb[ccol0];     by0 = cb[ccol0 + 1];
        bx1 = cb[ccol0 + 8]; by1 = cb[ccol0 + 9];
    }

    const int arow = lane & 15;
    const int acol = (lane >> 4) * 8;
    const int off0 = p16_off(q, ccol0);
    const int off1 = p16_off(q, ccol0 + 8);
    const int srow = tid >> 4;           // staging row 0..15
    const int scol = (tid & 15) * 8;     // staging col (halves)

    int mt = blockIdx.x;
    uint4 pre = make_uint4(0, 0, 0, 0);
    if (mt < M_TILES)
        pre = *(const uint4*)&g_h16[(size_t)(mt * 16 + srow) * 128 + scol];
    int buf = 0;

    while (mt < M_TILES) {
        // stage current tile into buffer `buf`
        *(uint4*)&S[(buf * 16 + srow) * 136 + scol] = pre;
        // prefetch next tile
        int nxt = mt + gridDim.x;
        if (nxt < M_TILES)
            pre = *(const uint4*)&g_h16[(size_t)(nxt * 16 + srow) * 128 + scol];
        __syncthreads();

        float acc0[4] = {0.f, 0.f, 0.f, 0.f};
        float acc1[4] = {0.f, 0.f, 0.f, 0.f};
        #pragma unroll
        for (int ks = 0; ks < 8; ++ks) {
            unsigned a[4];
            unsigned addr = sbase +
                ((unsigned)((buf * 16 + arow) * 136 + ks * 16 + acol) << 1);
            ldsm_x4(a[0], a[1], a[2], a[3], addr);
            mma16816(acc0, a, Bf[ks][0]);
            mma16816(acc1, a, Bf[ks][1]);
        }

        int r0 = mt * 16 + (lane >> 2);
        size_t base = (size_t)r0 * 512;
        __half2 v;
        v = __floats2half2_rn(acc0[0] + bx0, acc0[1] + by0);
        *(__half2*)&g_P16[base + off0] = v;
        v = __floats2half2_rn(acc1[0] + bx1, acc1[1] + by1);
        *(__half2*)&g_P16[base + off1] = v;
        base += 8 * 512;
        v = __floats2half2_rn(acc0[2] + bx0, acc0[3] + by0);
        *(__half2*)&g_P16[base + off0] = v;
        v = __floats2half2_rn(acc1[2] + bx1, acc1[3] + by1);
        *(__half2*)&g_P16[base + off1] = v;

        buf ^= 1;
        mt = nxt;
    }
}

// ---------------------------------------------------------------------------
// Kernel 3: edge stage — interleaved P16 (1 LDG.128/endpoint), fp16 W3 in
// shared, PACKED-PAIR shfl broadcast (2 edges per shfl, split via half-lane
// selectors), 4 edges/warp iter, persistent 1-wave grid, red.v4 scatter.
// ---------------------------------------------------------------------------
__global__ __launch_bounds__(128, 10) void edge_kernel(
    const void*  __restrict__ ei,
    const float* __restrict__ ef,
    const float* __restrict__ gw, const float* __restrict__ cw)
{
    // s_w[k][lane] = {g(d0,d1), g(d2,d3), c(d0,d1), c(d2,d3)} as half2s
    __shared__ uint4 s_w[DE][32];

    const int tid    = threadIdx.x;
    const int lane   = tid & 31;
    const int warp   = (blockIdx.x * blockDim.x + tid) >> 5;
    const int nwarps = (gridDim.x * blockDim.x) >> 5;
    const int is64   = g_is64;

    for (int i = tid; i < DE * 32; i += blockDim.x) {
        int k = i >> 5, p = i & 31;
        float4 g = *(const float4*)&gw[(size_t)(256 + k) * 128 + p * 4];
        float4 c = *(const float4*)&cw[(size_t)(256 + k) * 128 + p * 4];
        __half2 g0 = __floats2half2_rn(g.x, g.y);
        __half2 g1 = __floats2half2_rn(g.z, g.w);
        __half2 c0 = __floats2half2_rn(c.x, c.y);
        __half2 c1 = __floats2half2_rn(c.z, c.w);
        s_w[k][p] = make_uint4(*(unsigned*)&g0, *(unsigned*)&g1,
                               *(unsigned*)&c0, *(unsigned*)&c1);
    }
    __syncthreads();

    for (int e = warp * 4; e < N_EDGES; e += nwarps * 4) {
        int s[4], d[4];
        if (is64) {
            const long long* E = (const long long*)ei;
            #pragma unroll
            for (int j = 0; j < 4; ++j) {
                s[j] = (int)E[e + j];
                d[j] = (int)E[N_EDGES + e + j];
            }
        } else {
            const int* E = (const int*)ei;
            #pragma unroll
            for (int j = 0; j < 4; ++j) {
                s[j] = E[e + j];
                d[j] = E[N_EDGES + e + j];
            }
        }

        // 8 independent 16B gathers; accumulators init = g1+g2 / c1+c2
        __half2 rg0[4], rg1[4], rc0[4], rc1[4];
        #pragma unroll
        for (int j = 0; j < 4; ++j) {
            uint4 S4 = *(const uint4*)(g_P16 + (size_t)s[j] * 512 + lane * 8);
            uint4 D4 = *(const uint4*)(g_P16 + (size_t)d[j] * 512 + 256 + lane * 8);
            rg0[j] = __hadd2(*(__half2*)&S4.x, *(__half2*)&D4.x);
            rg1[j] = __hadd2(*(__half2*)&S4.y, *(__half2*)&D4.y);
            rc0[j] = __hadd2(*(__half2*)&S4.z, *(__half2*)&D4.z);
            rc1[j] = __hadd2(*(__half2*)&S4.w, *(__half2*)&D4.w);
        }

        // pair-packed edge features: evp[p] = (ev[2p], ev[2p+1]) as half2
        unsigned evp[2];
        #pragma unroll
        for (int p = 0; p < 2; ++p) {
            float eA = (lane < DE) ? ef[(size_t)(e + 2 * p) * DE + lane] : 0.f;
            float eB = (lane < DE) ? ef[(size_t)(e + 2 * p + 1) * DE + lane] : 0.f;
            __half2 t = __floats2half2_rn(eA, eB);
            evp[p] = *(unsigned*)&t;
        }

        // rank-10 update in half2; ONE shfl serves TWO edges (half-lane split)
        #pragma unroll
        for (int k = 0; k < DE; ++k) {
            uint4 wv = s_w[k][lane];
            __half2 wG0 = *(__half2*)&wv.x, wG1 = *(__half2*)&wv.y;
            __half2 wC0 = *(__half2*)&wv.z, wC1 = *(__half2*)&wv.w;
            #pragma unroll
            for (int p = 0; p < 2; ++p) {
                unsigned eku = __shfl_sync(0xffffffffu, evp[p], k);
                __half2 ek2 = *(__half2*)&eku;
                __half2 e0 = __low2half2(ek2);    // folds to .H0_H0
                __half2 e1 = __high2half2(ek2);   // folds to .H1_H1
                int j0 = 2 * p, j1 = 2 * p + 1;
                rg0[j0] = __hfma2(e0, wG0, rg0[j0]);
                rg1[j0] = __hfma2(e0, wG1, rg1[j0]);
                rc0[j0] = __hfma2(e0, wC0, rc0[j0]);
                rc1[j0] = __hfma2(e0, wC1, rc1[j0]);
                rg0[j1] = __hfma2(e1, wG0, rg0[j1]);
                rg1[j1] = __hfma2(e1, wG1, rg1[j1]);
                rc0[j1] = __hfma2(e1, wC0, rc0[j1]);
                rc1[j1] = __hfma2(e1, wC1, rc1[j1]);
            }
        }

        // activations (f32) + scatter; output cols = {4*lane..4*lane+3}
        #pragma unroll
        for (int j = 0; j < 4; ++j) {
            float2 gA = __half22float2(rg0[j]);
            float2 gB = __half22float2(rg1[j]);
            float2 cA = __half22float2(rc0[j]);
            float2 cB = __half22float2(rc1[j]);
            float4 m;
            m.x = sigmoid_f(gA.x) * softplus_f(cA.x);
            m.y = sigmoid_f(gA.y) * softplus_f(cA.y);
            m.z = sigmoid_f(gB.x) * softplus_f(cB.x);
            m.w = sigmoid_f(gB.y) * softplus_f(cB.y);
            float* o = g_agg + (size_t)s[j] * D + lane * 4;
            asm volatile("red.global.add.v4.f32 [%0], {%1,%2,%3,%4};"
                         :: "l"(o), "f"(m.x), "f"(m.y), "f"(m.z), "f"(m.w)
                         : "memory");
        }
    }
}

// ---------------------------------------------------------------------------
// Kernel 4a: BN stats stage 1 — 2048 blocks, thread d = channel d, 8-way ILP.
// NO atomics: per-block partials to g_part[d][b] (transposed for stage 2).
// ---------------------------------------------------------------------------
__global__ __launch_bounds__(128) void stats1_kernel() {
    const int d = threadIdx.x;   // blockDim = 128
    const int b = blockIdx.x;
    const int chunk = (N_NODES + NB1 - 1) / NB1;   // 25
    const int n0 = b * chunk;
    const int n1 = min(n0 + chunk, N_NODES);

    float s[8], q[8];
    #pragma unroll
    for (int u = 0; u < 8; ++u) { s[u] = 0.f; q[u] = 0.f; }

    int n = n0;
    for (; n + 8 <= n1; n += 8) {
        #pragma unroll
        for (int u = 0; u < 8; ++u) {
            float v = g_agg[(size_t)(n + u) * D + d];
            s[u] += v; q[u] = fmaf(v, v, q[u]);
        }
    }
    for (; n < n1; ++n) {
        float v = g_agg[(size_t)n * D + d];
        s[0] += v; q[0] = fmaf(v, v, q[0]);
    }
    float ss = ((s[0] + s[1]) + (s[2] + s[3])) + ((s[4] + s[5]) + (s[6] + s[7]));
    float qq = ((q[0] + q[1]) + (q[2] + q[3])) + ((q[4] + q[5]) + (q[6] + q[7]));
    g_part[d * NB1 + b] = ss;
    g_part[D * NB1 + d * NB1 + b] = qq;
}

// ---------------------------------------------------------------------------
// Kernel 4b: BN stats stage 2 — one block per channel, tree reduce, no atomics
// ---------------------------------------------------------------------------
__global__ __launch_bounds__(256) void stats2_kernel() {
    __shared__ float rs[256], rq[256];
    const int d = blockIdx.x;
    const int t = threadIdx.x;

    float s = 0.f, q = 0.f;
    #pragma unroll
    for (int b = t; b < NB1; b += 256) {
        s += g_part[d * NB1 + b];
        q += g_part[D * NB1 + d * NB1 + b];
    }
    rs[t] = s; rq[t] = q;
    __syncthreads();
    #pragma unroll
    for (int off = 128; off > 0; off >>= 1) {
        if (t < off) { rs[t] += rs[t + off]; rq[t] += rq[t + off]; }
        __syncthreads();
    }
    if (t == 0) {
        g_sum[d]   = (double)rs[0];
        g_sumsq[d] = (double)rq[0];
    }
}

// ---------------------------------------------------------------------------
// Kernel 5: BN affine fold (per-block, in smem) + apply + residual + softplus
// ---------------------------------------------------------------------------
__global__ __launch_bounds__(256) void final_kernel(
    const float* __restrict__ h,
    const float* __restrict__ gamma, const float* __restrict__ beta,
    float* __restrict__ out)
{
    __shared__ float sa[D], sb[D];
    if (threadIdx.x < D) {
        int d = threadIdx.x;
        double mean = g_sum[d] * (1.0 / N_NODES);
        double var  = g_sumsq[d] * (1.0 / N_NODES) - mean * mean;
        float invstd = rsqrtf((float)var + BN_EPS);
        float a = invstd * gamma[d];
        sa[d] = a;
        sb[d] = beta[d] - (float)mean * a;
    }
    __syncthreads();

    const int total4 = N_NODES * D / 4;
    for (int f4 = blockIdx.x * blockDim.x + threadIdx.x; f4 < total4;
         f4 += gridDim.x * blockDim.x) {
        int d4 = (f4 & 31) * 4;
        float4 av = ((const float4*)g_agg)[f4];
        float4 hv = ((const float4*)h)[f4];
        float4 aa = *(const float4*)&sa[d4];
        float4 bb = *(const float4*)&sb[d4];
        float4 r;
        r.x = softplus_f(hv.x + av.x * aa.x + bb.x);
        r.y = softplus_f(hv.y + av.y * aa.y + bb.y);
        r.z = softplus_f(hv.z + av.z * aa.z + bb.z);
        r.w = softplus_f(hv.w + av.w * aa.w + bb.w);
        ((float4*)out)[f4] = r;
    }
}

// ---------------------------------------------------------------------------
extern "C" void kernel_launch(void* const* d_in, const int* in_sizes, int n_in,
                              void* d_out, int out_size) {
    const float* h     = (const float*)d_in[0];
    const void*  ei    = d_in[1];
    const float* ef    = (const float*)d_in[2];
    const float* gw    = (const float*)d_in[3];
    const float* gb    = (const float*)d_in[4];
    const float* cw    = (const float*)d_in[5];
    const float* cb    = (const float*)d_in[6];
    const float* gamma = (const float*)d_in[7];
    const float* beta  = (const float*)d_in[8];
    float* out = (float*)d_out;

    prep_kernel<<<1024, 256>>>(h, gw, cw, (const int*)ei);
    dim3 gg(782, 4);
    node_gemm_tc<<<gg, 256>>>(gb, cb);
    edge_kernel<<<1480, 128>>>(ei, ef, gw, cw);
    stats1_kernel<<<NB1, 128>>>();
    stats2_kernel<<<D, 256>>>();
    final_kernel<<<1024, 256>>>(h, gamma, beta, out);
}